// round 8
// baseline (speedup 1.0000x reference)
#include <cuda_runtime.h>
#include <cuda_bf16.h>

// HungarianMatcher cost matrix, diagonal only.
//   out[b,q,t] = |cq-ct|+|wq-wt| - softmax(logits[b,q])[label_t] - gIoU(scaled)
// Latency-bound regime: 4 rows per warp, single-wave grid (640 blocks),
// software prefetch of the next row's logits behind current-row compute.

#define BS 64
#define NQ 300
#define NC 200
#define NT 32
#define WARPS 8
#define ROWS_PER_BLOCK 32              // WARPS * 4
#define QCHUNKS ((NQ + ROWS_PER_BLOCK - 1) / ROWS_PER_BLOCK)   // 10
#define NC4 (NC / 4)                   // 50 float4 per row

__global__ __launch_bounds__(WARPS * 32)
void matcher_kernel(const float* __restrict__ logits,
                    const float* __restrict__ pred_seg,
                    const float* __restrict__ tgt_seg,
                    const float* __restrict__ lengths,
                    const int*   __restrict__ labels32,
                    float* __restrict__ out)
{
    const int b     = blockIdx.y;
    const int qbase = blockIdx.x * ROWS_PER_BLOCK;
    const int warp  = threadIdx.x >> 5;
    const int lane  = threadIdx.x & 31;

    __shared__ __align__(16) float s_exp[WARPS][NC];
    __shared__ float s_tc[NT], s_tw[NT];   // target center/width (unscaled)
    __shared__ float s_ts[NT], s_te[NT];   // target start/end (scaled by L)
    __shared__ int   s_lab[NT];

    const float L = lengths[b];

    // First 32 threads: load targets; probe batch-0 labels for int32 vs int64
    // (JAX silently demotes int64 to int32; detect at runtime).
    if (threadIdx.x < NT) {
        const int t  = threadIdx.x;
        const int lo = labels32[2 * t];
        const int hi = labels32[2 * t + 1];
        const bool ok64 = (hi == 0) && ((unsigned)lo < (unsigned)NC);
        const unsigned m = __ballot_sync(0xffffffffu, ok64);
        const bool is64 = (m == 0xffffffffu);

        const int idx = b * NT + t;
        s_lab[t] = is64 ? labels32[2 * idx] : labels32[idx];

        const float c = tgt_seg[(size_t)idx * 2 + 0];
        const float w = tgt_seg[(size_t)idx * 2 + 1];
        s_tc[t] = c;
        s_tw[t] = w;
        const float cs = c * L;
        const float ws = w * L;
        s_ts[t] = cs - 0.5f * ws;
        s_te[t] = cs + 0.5f * ws;
    }
    __syncthreads();

    // Lane's two float4 slots in a row: v0 = lane (<50 always),
    // v1 = lane + 32 (valid only for lanes 0..17).
    const bool has2 = (lane + 32) < NC4;
    float4* __restrict__ s_exp4 = (float4*)s_exp[warp];

    int  q     = qbase + warp;            // rows q, q+8, q+16, q+24
    bool valid = q < NQ;

    // Prefetch row 0 of this warp's strip.
    float4 a0 = make_float4(0.f, 0.f, 0.f, 0.f), a1 = a0;
    float2 seg = make_float2(0.f, 0.f);
    if (valid) {
        const float4* r4 = (const float4*)(logits + ((size_t)b * NQ + q) * NC);
        a0 = r4[lane];
        if (has2) a1 = r4[lane + 32];
        seg = ((const float2*)pred_seg)[(size_t)b * NQ + q];
    }

    #pragma unroll
    for (int r = 0; r < ROWS_PER_BLOCK / WARPS; ++r) {
        if (!valid) break;

        // ---- prefetch next row before touching this row's data ----
        const int  qn    = q + WARPS;
        const bool vnext = (r + 1 < ROWS_PER_BLOCK / WARPS) && (qn < NQ);
        float4 b0 = make_float4(0.f, 0.f, 0.f, 0.f), b1 = b0;
        float2 segn = make_float2(0.f, 0.f);
        if (vnext) {
            const float4* r4 = (const float4*)(logits + ((size_t)b * NQ + qn) * NC);
            b0 = r4[lane];
            if (has2) b1 = r4[lane + 32];
            segn = ((const float2*)pred_seg)[(size_t)b * NQ + qn];
        }

        // ---- exps + denominator for row q ----
        float4 e0;
        e0.x = __expf(a0.x); e0.y = __expf(a0.y);
        e0.z = __expf(a0.z); e0.w = __expf(a0.w);
        s_exp4[lane] = e0;
        float sum = (e0.x + e0.y) + (e0.z + e0.w);
        if (has2) {
            float4 e1;
            e1.x = __expf(a1.x); e1.y = __expf(a1.y);
            e1.z = __expf(a1.z); e1.w = __expf(a1.w);
            s_exp4[lane + 32] = e1;
            sum += (e1.x + e1.y) + (e1.z + e1.w);
        }
        #pragma unroll
        for (int off = 16; off; off >>= 1)
            sum += __shfl_xor_sync(0xffffffffu, sum, off);
        const float inv_sum = 1.0f / sum;

        __syncwarp();   // s_exp visible across warp before label gather

        // ---- this query's segment ----
        const float cq  = seg.x;
        const float wq  = seg.y;
        const float cqs = cq * L;
        const float wqs = wq * L;
        const float s1  = cqs - 0.5f * wqs;
        const float e1s = cqs + 0.5f * wqs;
        const float len1 = e1s - s1;

        // ---- lane t handles target t (NT == 32) ----
        const int t = lane;
        const float cost_class = -s_exp[warp][s_lab[t]] * inv_sum;
        const float cost_seg   = fabsf(cq - s_tc[t]) + fabsf(wq - s_tw[t]);

        const float s2 = s_ts[t];
        const float e2 = s_te[t];
        float inter = fminf(e1s, e2) - fmaxf(s1, s2);
        inter = fmaxf(inter, 0.0f);
        const float uni = len1 + (e2 - s2) - inter;
        const float iou = inter / uni;
        const float enc = fmaxf(e1s, e2) - fminf(s1, s2);
        const float giou = iou - (enc - uni) / enc;

        out[((size_t)b * NQ + q) * NT + t] = cost_seg + cost_class - giou;

        __syncwarp();   // row done before s_exp reuse next iteration

        // ---- rotate pipeline ----
        a0 = b0; a1 = b1; seg = segn;
        q = qn; valid = vnext;
    }
}

extern "C" void kernel_launch(void* const* d_in, const int* in_sizes, int n_in,
                              void* d_out, int out_size)
{
    const float* logits   = (const float*)d_in[0];
    const float* pred_seg = (const float*)d_in[1];
    const float* tgt_seg  = (const float*)d_in[2];
    const float* lengths  = (const float*)d_in[3];
    const int*   labels   = (const int*)d_in[4];
    float*       out      = (float*)d_out;

    dim3 grid(QCHUNKS, BS);          // 10 x 64 = 640 blocks -> single wave
    dim3 block(WARPS * 32);
    matcher_kernel<<<grid, block>>>(logits, pred_seg, tgt_seg, lengths,
                                    labels, out);
}

// round 9
// speedup vs baseline: 1.2047x; 1.2047x over previous
#include <cuda_runtime.h>
#include <cuda_bf16.h>

// HungarianMatcher cost matrix, diagonal only.
//   out[b,q,t] = |cq-ct|+|wq-wt| - softmax(logits[b,q])[label_t] - gIoU(scaled)
//
// Stall-bound regime: no shared-memory exp spill (denominator computed
// spill-free; numerator re-gathered from L1-resident row), two rows per warp
// interleaved for ILP across the load/shuffle latency chains.

#define BS 64
#define NQ 300
#define NC 200
#define NT 32
#define WARPS 4
#define ROWS_PER_BLOCK (WARPS * 2)     // 8
#define QCHUNKS ((NQ + ROWS_PER_BLOCK - 1) / ROWS_PER_BLOCK)   // 38
#define NC4 (NC / 4)                   // 50 float4 per row

__global__ __launch_bounds__(WARPS * 32)
void matcher_kernel(const float* __restrict__ logits,
                    const float* __restrict__ pred_seg,
                    const float* __restrict__ tgt_seg,
                    const float* __restrict__ lengths,
                    const int*   __restrict__ labels32,
                    float* __restrict__ out)
{
    const int b    = blockIdx.y;
    const int warp = threadIdx.x >> 5;
    const int lane = threadIdx.x & 31;

    __shared__ float s_tc[NT], s_tw[NT];   // target center/width (unscaled)
    __shared__ float s_ts[NT], s_te[NT];   // target start/end (scaled by L)
    __shared__ int   s_lab[NT];

    const float L = lengths[b];

    // First 32 threads: load targets; probe batch-0 labels for int32 vs int64
    // (JAX silently demotes int64 to int32; detect at runtime).
    if (threadIdx.x < NT) {
        const int t  = threadIdx.x;
        const int lo = labels32[2 * t];
        const int hi = labels32[2 * t + 1];
        const bool ok64 = (hi == 0) && ((unsigned)lo < (unsigned)NC);
        const unsigned m = __ballot_sync(0xffffffffu, ok64);
        const bool is64 = (m == 0xffffffffu);

        const int idx = b * NT + t;
        s_lab[t] = is64 ? labels32[2 * idx] : labels32[idx];

        const float c = tgt_seg[(size_t)idx * 2 + 0];
        const float w = tgt_seg[(size_t)idx * 2 + 1];
        s_tc[t] = c;
        s_tw[t] = w;
        const float cs = c * L;
        const float ws = w * L;
        s_ts[t] = cs - 0.5f * ws;
        s_te[t] = cs + 0.5f * ws;
    }
    __syncthreads();

    // Two rows per warp: q0 = base + 2*warp, q1 = q0 + 1.
    const int q0 = blockIdx.x * ROWS_PER_BLOCK + 2 * warp;
    const int q1 = q0 + 1;
    const bool v0 = q0 < NQ;
    const bool v1 = q1 < NQ;
    if (!v0) return;                      // q0 invalid implies q1 invalid

    const float* __restrict__ row0 = logits + ((size_t)b * NQ + q0) * NC;
    const float* __restrict__ row1 = logits + ((size_t)b * NQ + q1) * NC;
    const float4* __restrict__ r40 = (const float4*)row0;
    const float4* __restrict__ r41 = (const float4*)row1;

    const bool has2 = (lane + 32) < NC4;  // lanes 0..17 own a 2nd float4

    // ---- issue all row loads up front (MLP = 4) ----
    float4 a0 = r40[lane];
    float4 c0 = v1 ? r41[lane] : make_float4(0.f, 0.f, 0.f, 0.f);
    float4 a1 = make_float4(0.f, 0.f, 0.f, 0.f), c1 = a1;
    if (has2) {
        a1 = r40[lane + 32];
        if (v1) c1 = r41[lane + 32];
    }
    float2 sg0 = ((const float2*)pred_seg)[(size_t)b * NQ + q0];
    float2 sg1 = v1 ? ((const float2*)pred_seg)[(size_t)b * NQ + q1]
                    : make_float2(0.f, 0.f);

    // ---- gather logits at label positions (L1-hot after row loads) ----
    const int  lab = s_lab[lane];
    const float g0 = row0[lab];
    const float g1 = v1 ? row1[lab] : 0.f;

    // ---- exps, interleaved across both rows for ILP ----
    float s0 = 0.f, s1 = 0.f;
    {
        float4 e;
        e.x = __expf(a0.x); e.y = __expf(a0.y);
        e.z = __expf(a0.z); e.w = __expf(a0.w);
        s0 = (e.x + e.y) + (e.z + e.w);
        e.x = __expf(c0.x); e.y = __expf(c0.y);
        e.z = __expf(c0.z); e.w = __expf(c0.w);
        s1 = (e.x + e.y) + (e.z + e.w);
        if (has2) {
            e.x = __expf(a1.x); e.y = __expf(a1.y);
            e.z = __expf(a1.z); e.w = __expf(a1.w);
            s0 += (e.x + e.y) + (e.z + e.w);
            e.x = __expf(c1.x); e.y = __expf(c1.y);
            e.z = __expf(c1.z); e.w = __expf(c1.w);
            s1 += (e.x + e.y) + (e.z + e.w);
        }
    }

    // ---- interleaved butterfly reductions (two independent chains) ----
    #pragma unroll
    for (int off = 16; off; off >>= 1) {
        s0 += __shfl_xor_sync(0xffffffffu, s0, off);
        s1 += __shfl_xor_sync(0xffffffffu, s1, off);
    }
    const float cls0 = -__expf(g0) / s0;        // -softmax[lab] for row q0
    const float cls1 = -__expf(g1) / s1;        // row q1

    // ---- epilogue: lane t handles target t for both rows ----
    const int t = lane;
    const float tc = s_tc[t], tw = s_tw[t];
    const float s2 = s_ts[t], e2 = s_te[t];
    const float tlen = e2 - s2;

    {   // row q0
        const float cq = sg0.x, wq = sg0.y;
        const float cqs = cq * L, wqs = wq * L;
        const float s1s = cqs - 0.5f * wqs;
        const float e1s = cqs + 0.5f * wqs;
        float inter = fminf(e1s, e2) - fmaxf(s1s, s2);
        inter = fmaxf(inter, 0.0f);
        const float uni = (e1s - s1s) + tlen - inter;
        const float enc = fmaxf(e1s, e2) - fminf(s1s, s2);
        const float giou = inter / uni - (enc - uni) / enc;
        const float cost = fabsf(cq - tc) + fabsf(wq - tw) + cls0 - giou;
        out[((size_t)b * NQ + q0) * NT + t] = cost;
    }
    if (v1) {   // row q1
        const float cq = sg1.x, wq = sg1.y;
        const float cqs = cq * L, wqs = wq * L;
        const float s1s = cqs - 0.5f * wqs;
        const float e1s = cqs + 0.5f * wqs;
        float inter = fminf(e1s, e2) - fmaxf(s1s, s2);
        inter = fmaxf(inter, 0.0f);
        const float uni = (e1s - s1s) + tlen - inter;
        const float enc = fmaxf(e1s, e2) - fminf(s1s, s2);
        const float giou = inter / uni - (enc - uni) / enc;
        const float cost = fabsf(cq - tc) + fabsf(wq - tw) + cls1 - giou;
        out[((size_t)b * NQ + q1) * NT + t] = cost;
    }
}

extern "C" void kernel_launch(void* const* d_in, const int* in_sizes, int n_in,
                              void* d_out, int out_size)
{
    const float* logits   = (const float*)d_in[0];
    const float* pred_seg = (const float*)d_in[1];
    const float* tgt_seg  = (const float*)d_in[2];
    const float* lengths  = (const float*)d_in[3];
    const int*   labels   = (const int*)d_in[4];
    float*       out      = (float*)d_out;

    dim3 grid(QCHUNKS, BS);          // 38 x 64 = 2432 blocks
    dim3 block(WARPS * 32);          // 128 threads
    matcher_kernel<<<grid, block>>>(logits, pred_seg, tgt_seg, lengths,
                                    labels, out);
}